// round 12
// baseline (speedup 1.0000x reference)
#include <cuda_runtime.h>
#include <math.h>
#include <stdint.h>

#define BB 8
#define AA 64
#define DE 128
#define MM 512
#define DH 64
#define ZD 128

#define SMQ 16         // m per stage
#define NBUF 3         // smem buffers
#define NST 16         // stages per CTA (256 m / 16)
#define HALF 256       // m per CTA

__device__ float g_dH2[BB * MM];
__device__ float g_logv[BB * MM * DH];
// partial states: per pidx (0..1023): mx, sm + e-acc + v-acc
__device__ float g_pm[2 * BB * AA * 2];
__device__ float g_pe[2 * BB * AA * DE];
__device__ float g_pv[2 * BB * AA * DH];

__device__ __forceinline__ float warp_sum(float v) {
#pragma unroll
    for (int o = 16; o > 0; o >>= 1) v += __shfl_xor_sync(0xffffffffu, v, o);
    return v;
}

__device__ __forceinline__ void cp16(unsigned int dst, const void* src) {
    asm volatile("cp.async.cg.shared.global [%0], [%1], 16;\n" :: "r"(dst), "l"(src));
}
__device__ __forceinline__ void cp_commit() {
    asm volatile("cp.async.commit_group;\n" ::: "memory");
}
__device__ __forceinline__ void cp_wait1() {
    asm volatile("cp.async.wait_group 1;\n" ::: "memory");
}

// ---------------------------------------------------------------------------
// Prologue: per (b,m) Poincare dH2 + log-map vector. One warp per (b,m).
// ---------------------------------------------------------------------------
__global__ void __launch_bounds__(256) prologue_kernel(
    const float* __restrict__ currH,   // [B, DH]
    const float* __restrict__ demoH)   // [B*M, DH]
{
    int gw = blockIdx.x * 8 + (threadIdx.x >> 5);
    int l = threadIdx.x & 31;
    if (gw >= BB * MM) return;
    int b = gw >> 9;

    float x0 = currH[b * DH + 2 * l], x1 = currH[b * DH + 2 * l + 1];
    float y0 = demoH[(size_t)gw * DH + 2 * l], y1 = demoH[(size_t)gw * DH + 2 * l + 1];

    const float thr = 1.0f - 1e-5f;
    float x2 = warp_sum(x0 * x0 + x1 * x1);
    float nx = fmaxf(sqrtf(x2), 1e-15f);
    if (nx > thr) { float s = thr / nx; x0 *= s; x1 *= s; x2 *= s * s; }
    float y2 = warp_sum(y0 * y0 + y1 * y1);
    float ny = fmaxf(sqrtf(y2), 1e-15f);
    if (ny > thr) { float s = thr / ny; y0 *= s; y1 *= s; y2 *= s * s; }

    float xy = warp_sum(x0 * y0 + x1 * y1);

    float Ac = 1.0f - 2.0f * xy + y2;
    float Bc = 1.0f - x2;
    float den = fmaxf(1.0f - 2.0f * xy + x2 * y2, 1e-15f);
    float inv = 1.0f / den;
    float u0 = (Bc * y0 - Ac * x0) * inv;
    float u1 = (Bc * y1 - Ac * x1) * inv;

    float un2 = warp_sum(u0 * u0 + u1 * u1);
    float un = fmaxf(sqrtf(un2), 1e-15f);
    float arg = fminf(un, 1.0f - 1e-7f);
    float at = atanhf(arg);

    if (l == 0) g_dH2[gw] = 4.0f * at * at;

    float sc = fmaxf(1.0f - x2, 1e-15f) * at / un;
    g_logv[(size_t)gw * DH + 2 * l]     = sc * u0;
    g_logv[(size_t)gw * DH + 2 * l + 1] = sc * u1;
}

// ---------------------------------------------------------------------------
// Main: grid 1024 = (b,a) x 2 m-halves; 256 threads / 8 warps.
// cp.async pipeline: 16 stages x 16 m; 3 buffers; lookahead 2.
// Warp w consumes rows w and w+8 of each stage; online softmax; partial
// (mx, sm, e-acc, v-acc) written unnormalized to device scratch.
// ---------------------------------------------------------------------------
__global__ void __launch_bounds__(256, 5) main_kernel(
    const float* __restrict__ curr_rho,  // [B, A, DE]
    const float* __restrict__ demo_rho)  // [B, M, A, DE]
{
    const int pidx = blockIdx.x;          // 0..1023
    const int bx = pidx >> 1, half = pidx & 1;
    const int b = bx >> 6, a = bx & 63;
    const int mb = half * HALF;
    const int tid = threadIdx.x;
    const int w = tid >> 5, l = tid & 31;

    __shared__ float sd[NBUF][SMQ][DE];   // 24 KB
    __shared__ float sl[NBUF][SMQ][DH];   // 12 KB
    __shared__ float s_h2[HALF];          //  1 KB
    __shared__ float s_mx[8], s_sm[8];
    __shared__ float s_acce[8][DE];       //  4 KB
    __shared__ float s_accv[8][DH];       //  2 KB

    s_h2[tid] = g_dH2[b * MM + mb + tid];

    // cp.async source/dest: demo rows r0 = tid>>5, r1 = r0+8, chunk c = tid&31
    const int r0 = tid >> 5, c = tid & 31;
    const float* d_src0 = demo_rho + (((size_t)(b * MM + mb + r0)) * AA + a) * DE + 4 * c;
    const float* d_src1 = d_src0 + (size_t)8 * AA * DE;
    unsigned int d_dst0 = (unsigned int)__cvta_generic_to_shared(&sd[0][r0][4 * c]);
    unsigned int d_dst1 = (unsigned int)__cvta_generic_to_shared(&sd[0][r0 + 8][4 * c]);
    // logv: row lr = tid>>4 (0..15), chunk lc = tid&15
    const int lr = tid >> 4, lc = tid & 15;
    const float* l_src0 = g_logv + ((size_t)(b * MM + mb + lr)) * DH + 4 * lc;
    unsigned int l_dst0 = (unsigned int)__cvta_generic_to_shared(&sl[0][lr][4 * lc]);
    const size_t d_step = (size_t)SMQ * AA * DE;   // floats per stage
    const size_t l_step = (size_t)SMQ * DH;
    const unsigned int sd_bytes = SMQ * DE * 4, sl_bytes = SMQ * DH * 4;

    // issue stages 0..1
#pragma unroll
    for (int q = 0; q < 2; q++) {
        unsigned int bo = (unsigned int)(q % NBUF);
        cp16(d_dst0 + bo * sd_bytes, d_src0 + (size_t)q * d_step);
        cp16(d_dst1 + bo * sd_bytes, d_src1 + (size_t)q * d_step);
        cp16(l_dst0 + bo * sl_bytes, l_src0 + (size_t)q * l_step);
        cp_commit();
    }

    const float4 cur = reinterpret_cast<const float4*>(curr_rho)[(size_t)bx * (DE / 4) + l];

    float mx = -3.0e38f, sm = 0.f;
    float4 ae = make_float4(0.f, 0.f, 0.f, 0.f);
    float av0 = 0.f, av1 = 0.f;

    for (int k = 0; k < NST; k++) {
        cp_wait1();
        __syncthreads();
        const int buf = k % NBUF;

#pragma unroll
        for (int t = 0; t < 2; t++) {
            const int row = w + 8 * t;
            float4 dv = *reinterpret_cast<const float4*>(&sd[buf][row][4 * l]);
            float2 lv = *reinterpret_cast<const float2*>(&sl[buf][row][2 * l]);
            float h2m = s_h2[SMQ * k + row];

            float d0 = cur.x - dv.x, d1 = cur.y - dv.y;
            float d2 = cur.z - dv.z, d3 = cur.w - dv.w;
            float part = (d0 * d0 + d1 * d1) + (d2 * d2 + d3 * d3);
            part += __shfl_xor_sync(0xffffffffu, part, 1);
            part += __shfl_xor_sync(0xffffffffu, part, 2);
            part += __shfl_xor_sync(0xffffffffu, part, 4);
            part += __shfl_xor_sync(0xffffffffu, part, 8);
            part += __shfl_xor_sync(0xffffffffu, part, 16);
            float s = -(part + h2m);            // warp-uniform

            if (s > mx) {                       // warp-uniform branch
                float cc = __expf(mx - s);
                mx = s;
                sm *= cc;
                ae.x *= cc; ae.y *= cc; ae.z *= cc; ae.w *= cc;
                av0 *= cc; av1 *= cc;
            }
            float p = __expf(s - mx);
            sm += p;
            ae.x += p * dv.x; ae.y += p * dv.y;
            ae.z += p * dv.z; ae.w += p * dv.w;
            av0 += p * lv.x;  av1 += p * lv.y;
        }

        // issue stage k+2 into buffer (k+2)%3 == (k-1)%3 (consumed last iter)
        if (k + 2 < NST) {
            unsigned int bo = (unsigned int)((k + 2) % NBUF);
            cp16(d_dst0 + bo * sd_bytes, d_src0 + (size_t)(k + 2) * d_step);
            cp16(d_dst1 + bo * sd_bytes, d_src1 + (size_t)(k + 2) * d_step);
            cp16(l_dst0 + bo * sl_bytes, l_src0 + (size_t)(k + 2) * l_step);
        }
        cp_commit();
    }

    // store 8 warp states
    if (l == 0) { s_mx[w] = mx; s_sm[w] = sm; }
    *reinterpret_cast<float4*>(&s_acce[w][4 * l]) = ae;
    s_accv[w][2 * l] = av0; s_accv[w][2 * l + 1] = av1;
    __syncthreads();

    // CTA-level merge of 8 states -> unnormalized partial to scratch
    float gmax = -3.0e38f;
#pragma unroll
    for (int q = 0; q < 8; q++) gmax = fmaxf(gmax, s_mx[q]);
    float Sc = 0.f;
#pragma unroll
    for (int q = 0; q < 8; q++) Sc += __expf(s_mx[q] - gmax) * s_sm[q];

    if (tid < DE) {
        float e = 0.f;
#pragma unroll
        for (int q = 0; q < 8; q++) e += __expf(s_mx[q] - gmax) * s_acce[q][tid];
        g_pe[(size_t)pidx * DE + tid] = e;
    } else if (tid < DE + DH) {
        int d = tid - DE;
        float v = 0.f;
#pragma unroll
        for (int q = 0; q < 8; q++) v += __expf(s_mx[q] - gmax) * s_accv[q][d];
        g_pv[(size_t)pidx * DH + d] = v;
    } else if (tid == DE + DH) {
        g_pm[pidx * 2 + 0] = gmax;
        g_pm[pidx * 2 + 1] = Sc;
    }
}

// ---------------------------------------------------------------------------
// Merge: 512 CTAs x 128 threads. Merge the two halves' partial softmax
// states, then exp-map + GEMVs + LayerNorm.
// ---------------------------------------------------------------------------
__global__ void __launch_bounds__(128) merge_kernel(
    const float* __restrict__ currH,     // [B, DH]
    const float* __restrict__ We,        // [64, DE]
    const float* __restrict__ Wh,        // [64, DH]
    const float* __restrict__ gamma,     // [ZD]
    const float* __restrict__ beta,      // [ZD]
    float* __restrict__ out)             // [B, A, ZD]
{
    const int bx = blockIdx.x;
    const int b = bx >> 6;
    const int tid = threadIdx.x;
    const int w = tid >> 5, l = tid & 31;

    __shared__ float s_eout[DE];
    __shared__ float s_v[DH];
    __shared__ float s_h[DH];
    __shared__ float s_red[8];

    float mx0 = g_pm[4 * bx + 0], sm0 = g_pm[4 * bx + 1];
    float mx1 = g_pm[4 * bx + 2], sm1 = g_pm[4 * bx + 3];
    float gm = fmaxf(mx0, mx1);
    float e0 = __expf(mx0 - gm), e1 = __expf(mx1 - gm);
    float invS = 1.0f / (e0 * sm0 + e1 * sm1);

    s_eout[tid] = (e0 * g_pe[(size_t)(2 * bx) * DE + tid]
                 + e1 * g_pe[(size_t)(2 * bx + 1) * DE + tid]) * invS;
    if (tid < DH)
        s_v[tid] = (e0 * g_pv[(size_t)(2 * bx) * DH + tid]
                  + e1 * g_pv[(size_t)(2 * bx + 1) * DH + tid]) * invS;
    __syncthreads();

    // exp-map on warp 0 (lane l owns dims 2l, 2l+1)
    if (w == 0) {
        float x0 = currH[b * DH + 2 * l], x1 = currH[b * DH + 2 * l + 1];
        const float thr = 1.0f - 1e-5f;
        float x2 = warp_sum(x0 * x0 + x1 * x1);
        float nx = fmaxf(sqrtf(x2), 1e-15f);
        if (nx > thr) { float s0 = thr / nx; x0 *= s0; x1 *= s0; x2 *= s0 * s0; }
        float lam = 2.0f / fmaxf(1.0f - x2, 1e-15f);

        float v0 = s_v[2 * l], v1 = s_v[2 * l + 1];
        float vn2 = warp_sum(v0 * v0 + v1 * v1);
        float vn = fmaxf(sqrtf(vn2), 1e-15f);
        float fac = tanhf(lam * vn * 0.5f);
        float iv = fac / vn;
        float y0 = v0 * iv, y1 = v1 * iv;

        float yn2 = warp_sum(y0 * y0 + y1 * y1);
        float yn = fmaxf(sqrtf(yn2), 1e-15f);
        if (yn > thr) { float s0 = thr / yn; y0 *= s0; y1 *= s0; yn2 *= s0 * s0; }

        float xy = warp_sum(x0 * y0 + x1 * y1);
        float den = fmaxf(1.0f + 2.0f * xy + x2 * yn2, 1e-15f);
        float ca = (1.0f + 2.0f * xy + yn2) / den;
        float cb2 = (1.0f - x2) / den;
        float o0 = ca * x0 + cb2 * y0, o1 = ca * x1 + cb2 * y1;

        float on2 = warp_sum(o0 * o0 + o1 * o1);
        float on = fmaxf(sqrtf(on2), 1e-15f);
        if (on > thr) { float s0 = thr / on; o0 *= s0; o1 *= s0; }
        s_h[2 * l] = o0; s_h[2 * l + 1] = o1;
    }
    __syncthreads();

    // GEMVs + LayerNorm
    float zj;
    if (tid < 64) {
        const float* wr = We + tid * DE;
        float acc = 0.f;
#pragma unroll 8
        for (int d = 0; d < DE; d++) acc += wr[d] * s_eout[d];
        zj = acc;
    } else {
        const float* wr = Wh + (tid - 64) * DH;
        float acc = 0.f;
#pragma unroll 8
        for (int d = 0; d < DH; d++) acc += wr[d] * s_h[d];
        zj = acc;
    }
    float p1 = warp_sum(zj);
    float p2 = warp_sum(zj * zj);
    if (l == 0) { s_red[w] = p1; s_red[4 + w] = p2; }
    __syncthreads();
    float sum = s_red[0] + s_red[1] + s_red[2] + s_red[3];
    float sq  = s_red[4] + s_red[5] + s_red[6] + s_red[7];
    float mean = sum * (1.0f / ZD);
    float var = sq * (1.0f / ZD) - mean * mean;
    float r = rsqrtf(var + 1e-5f);
    out[(size_t)bx * ZD + tid] = (zj - mean) * r * gamma[tid] + beta[tid];
}

extern "C" void kernel_launch(void* const* d_in, const int* in_sizes, int n_in,
                              void* d_out, int out_size) {
    const float* curr_rho = (const float*)d_in[0];
    const float* currH    = (const float*)d_in[1];
    const float* demo_rho = (const float*)d_in[2];
    const float* demoH    = (const float*)d_in[3];
    const float* We       = (const float*)d_in[4];
    const float* Wh       = (const float*)d_in[5];
    const float* gamma    = (const float*)d_in[6];
    const float* beta     = (const float*)d_in[7];
    float* out = (float*)d_out;

    prologue_kernel<<<512, 256>>>(currH, demoH);
    main_kernel<<<2 * BB * AA, 256>>>(curr_rho, demo_rho);
    merge_kernel<<<BB * AA, 128>>>(currH, We, Wh, gamma, beta, out);
}